// round 15
// baseline (speedup 1.0000x reference)
#include <cuda_runtime.h>
#include <cuda_bf16.h>
#include <stdint.h>

#define FULLMASK 0xFFFFFFFFu

constexpr int HWN     = 3136;   // 56*56
constexpr int NCH     = 512;
constexpr int NBATCH  = 32;
constexpr int CPB     = 4;      // channels per block (8 warps per channel)
constexpr int THREADS = 1024;
constexpr int KSEL    = 627;    // round(0.2*3136)
constexpr int RBRANK  = HWN - KSEL + 1;  // bottom-end rank from largest
constexpr int STRIDE  = 3140;   // smem row stride (u32), 16B aligned
constexpr int NQ      = HWN / 4;        // 784 uint4 per row
constexpr int QQ      = NQ / 8;         // 98 uint4 per warp eighth
constexpr int QELEM   = QQ * 4;         // 392 elements per eighth
constexpr int H0SZ    = 1152;   // 1024 bins in 36-word groups (uint4-walkable)
constexpr int HSTR    = H0SZ + 16;      // + spare; bufA/bufB overlay inside h0
constexpr int SMEM_WORDS = CPB * STRIDE + CPB * HSTR;
constexpr float ALPHA = 0.7f;

__device__ __forceinline__ float key2f(unsigned u) {
    return __uint_as_float((u & 0x80000000u) ? (u & 0x7FFFFFFFu) : ~u);
}
// branch-free monotone key from float bits
__device__ __forceinline__ unsigned mkey(unsigned b) {
    return b ^ ((unsigned)(((int)b) >> 31) | 0x80000000u);
}
// padded index: 1024-bin histo, 36 words per 32 bins
__device__ __forceinline__ int h0idx(unsigned bin) {
    return (int)(bin + ((bin >> 5) << 2));
}
// padded index: 256-bin histo, 12 words per 8 bins
__device__ __forceinline__ int hidx(unsigned bin) {
    return (int)(bin + ((bin >> 3) << 2));
}

__device__ __forceinline__ float wredf(float v) {
#pragma unroll
    for (int d = 16; d; d >>= 1) v += __shfl_xor_sync(FULLMASK, v, d);
    return v;
}

// per-channel barrier: 8 warps (256 threads), barrier id = channel+1
__device__ __forceinline__ void chbar(int id) {
    asm volatile("bar.sync %0, %1;" :: "r"(id), "r"(256) : "memory");
}

// ---- 1024-bin walk over 36-word-padded layout. rank r 1-based FROM LARGEST.
// Returns (bin, rankInBin, countOfBin). Conflict-free (uint4 stage1, stride-1 stage2).
__device__ __forceinline__ int3 walk1024(const unsigned* h, int lane, int r)
{
    const uint4* hv = reinterpret_cast<const uint4*>(h) + lane * 9; // 36 words
    int s = 0;
#pragma unroll
    for (int j = 0; j < 8; j++) {
        uint4 u = hv[j];
        s += (int)(u.x + u.y + u.z + u.w);
    }
    int incl = s;                            // suffix sum over lanes >= lane
#pragma unroll
    for (int d = 1; d < 32; d <<= 1) {
        int v = __shfl_down_sync(FULLMASK, incl, d);
        if (lane + d < 32) incl += v;
    }
    int hi = incl - s;
    bool sel = (hi < r) && (r <= hi + s);
    unsigned bal = __ballot_sync(FULLMASK, sel);
    int L = __ffs((int)bal) - 1;
    int rloc = __shfl_sync(FULLMASK, r - hi, L);
    int c2 = (int)h[L * 36 + lane];          // stride-1: conflict-free
    int incl2 = c2;
#pragma unroll
    for (int d = 1; d < 32; d <<= 1) {
        int v = __shfl_down_sync(FULLMASK, incl2, d);
        if (lane + d < 32) incl2 += v;
    }
    int hi2 = incl2 - c2;
    bool sel2 = (hi2 < rloc) && (rloc <= hi2 + c2);
    unsigned bal2 = __ballot_sync(FULLMASK, sel2);
    int L2 = __ffs((int)bal2) - 1;
    int bin = L * 32 + L2;
    int rr  = __shfl_sync(FULLMASK, rloc - hi2, L2);
    int cc  = __shfl_sync(FULLMASK, c2, L2);
    return make_int3(bin, rr, cc);
}

// ---- 256-bin packed walk over 12-word-padded layout (low16/high16 by shift).
__device__ __forceinline__ int3 walk(const unsigned* hist, int shift, int lane, int r)
{
    const uint4* hv = reinterpret_cast<const uint4*>(hist) + lane * 3; // 12 words
    uint4 a = hv[0], bq = hv[1];
    unsigned c[8] = { (a.x  >> shift) & 0xFFFFu, (a.y  >> shift) & 0xFFFFu,
                      (a.z  >> shift) & 0xFFFFu, (a.w  >> shift) & 0xFFFFu,
                      (bq.x >> shift) & 0xFFFFu, (bq.y >> shift) & 0xFFFFu,
                      (bq.z >> shift) & 0xFFFFu, (bq.w >> shift) & 0xFFFFu };
    int s = 0;
#pragma unroll
    for (int j = 0; j < 8; j++) s += (int)c[j];
    int incl = s;
#pragma unroll
    for (int d = 1; d < 32; d <<= 1) {
        int v = __shfl_down_sync(FULLMASK, incl, d);
        if (lane + d < 32) incl += v;
    }
    int hi = incl - s;
    bool sel = (hi < r) && (r <= hi + s);
    unsigned bal = __ballot_sync(FULLMASK, sel);
    int L = __ffs((int)bal) - 1;
    int bin = -1, rr = 0, cc = 0;
    if (lane == L) {
        int rloc = r - hi, cum = 0;
#pragma unroll
        for (int j = 7; j >= 0; j--) {
            if (bin < 0 && rloc <= cum + (int)c[j]) { bin = j; rr = rloc - cum; cc = (int)c[j]; }
            cum += (int)c[j];
        }
        bin += lane * 8;
    }
    bin = __shfl_sync(FULLMASK, bin, L);
    rr  = __shfl_sync(FULLMASK, rr,  L);
    cc  = __shfl_sync(FULLMASK, cc,  L);
    return make_int3(bin, rr, cc);
}

extern __shared__ unsigned smem[];

__global__ void __launch_bounds__(THREADS, 2)
wildcat_kernel(const float* __restrict__ x, float* __restrict__ out)
{
    unsigned* vals = smem;                   // CPB * STRIDE (raw float bits)
    unsigned* hist = smem + CPB * STRIDE;    // CPB * HSTR

    const int t    = threadIdx.x;
    const int lane = t & 31;
    const int warp = t >> 5;                 // 0..31
    const int w    = warp >> 3;              // channel 0..3
    const int q    = warp & 7;               // eighth of the spatial row
    const int bar  = w + 1;
    const int b    = blockIdx.x >> 7;        // batch
    const int c0   = (blockIdx.x & 127) * CPB;

    for (int i = t; i < CPB * HSTR; i += THREADS) hist[i] = 0;
    __syncthreads();

    // ---- load + transpose + FUSED 10-bit L0 histogram (raw atomics) --------
    {
        const float4* src = reinterpret_cast<const float4*>(
            x + (size_t)b * HWN * NCH + c0);
#pragma unroll
        for (int i = 0; i < 3; i++) {        // 3 full, unconditional iterations
            int hw = t + i * 1024;
            float4 v = src[(size_t)hw * (NCH / 4)];
            unsigned k0 = __float_as_uint(v.x), k1 = __float_as_uint(v.y);
            unsigned k2 = __float_as_uint(v.z), k3 = __float_as_uint(v.w);
            vals[0 * STRIDE + hw] = k0;
            vals[1 * STRIDE + hw] = k1;
            vals[2 * STRIDE + hw] = k2;
            vals[3 * STRIDE + hw] = k3;
            atomicAdd(&hist[0 * HSTR + h0idx(mkey(k0) >> 22)], 1u);
            atomicAdd(&hist[1 * HSTR + h0idx(mkey(k1) >> 22)], 1u);
            atomicAdd(&hist[2 * HSTR + h0idx(mkey(k2) >> 22)], 1u);
            atomicAdd(&hist[3 * HSTR + h0idx(mkey(k3) >> 22)], 1u);
        }
        if (t < 64) {                        // tail: hw in [3072, 3136)
            int hw = t + 3072;
            float4 v = src[(size_t)hw * (NCH / 4)];
            unsigned k0 = __float_as_uint(v.x), k1 = __float_as_uint(v.y);
            unsigned k2 = __float_as_uint(v.z), k3 = __float_as_uint(v.w);
            vals[0 * STRIDE + hw] = k0;
            vals[1 * STRIDE + hw] = k1;
            vals[2 * STRIDE + hw] = k2;
            vals[3 * STRIDE + hw] = k3;
            atomicAdd(&hist[0 * HSTR + h0idx(mkey(k0) >> 22)], 1u);
            atomicAdd(&hist[1 * HSTR + h0idx(mkey(k1) >> 22)], 1u);
            atomicAdd(&hist[2 * HSTR + h0idx(mkey(k2) >> 22)], 1u);
            atomicAdd(&hist[3 * HSTR + h0idx(mkey(k3) >> 22)], 1u);
        }
    }
    __syncthreads();                         // last block-wide barrier

    // ---- per-channel selection (channels decoupled from here) --------------
    unsigned* rowU  = vals + w * STRIDE;
    const uint4* row4 = reinterpret_cast<const uint4*>(rowU);
    unsigned* h0    = hist + w * HSTR;       // padded 1024-bin L0
    unsigned* bufA  = h0;                    // overlay: 384 words (after L0 walk)
    unsigned* bufB  = h0 + 384;              // overlay: 384 words
    unsigned* spare = h0 + H0SZ;             // 16 words, outside overlay
    const int qBase = q * QQ;
    const int eBase = q * QELEM;
    const int cid   = (q << 5) | lane;       // 0..255 thread id within channel

    int rT = 0;                              // live in q0
    int rB = 0;                              // live in q1

    // L0 walks: top on q0, bottom on q1
    if (q == 0) {
        int3 st = walk1024(h0, lane, KSEL);
        rT = st.y;
        if (lane == 0) spare[0] = (unsigned)st.x;
    } else if (q == 1) {
        int3 sb = walk1024(h0, lane, RBRANK);
        rB = sb.y;
        if (lane == 0) spare[1] = (unsigned)sb.x;
    }
    chbar(bar);
    const int selT = (int)spare[0];          // 10-bit logical bins
    const int selB = (int)spare[1];

    // zero the bufA/bufB overlay region (L0 histogram is dead now)
    for (int i = cid; i < 768; i += 256) h0[i] = 0;
    chbar(bar);

    // ---- L1: full scan: sure-sums + compaction + hist(B, bits 21..14) ------
    float sg = 0.f, sl = 0.f;
    unsigned cnt = 0;                        // compacted count (warp-uniform)
#pragma unroll 1
    for (int i = 0; i < 4; i++) {
        const bool valid = (i < 3) || (lane < (QQ - 96));
        uint4 kv = valid ? row4[qBase + i * 32 + lane] : make_uint4(0u, 0u, 0u, 0u);
        unsigned ks[4] = {kv.x, kv.y, kv.z, kv.w};
#pragma unroll
        for (int e = 0; e < 4; e++) {
            unsigned bb = ks[e];
            unsigned kk = mkey(bb);
            int bin = (int)(kk >> 22);
            float v = __uint_as_float(bb);
            if (valid && bin > selT) sg += v;
            if (valid && bin < selB) sl += v;
            unsigned add = (valid && bin == selT ? 1u : 0u)
                         + (valid && bin == selB ? 0x10000u : 0u);
            if (add) atomicAdd(&bufB[hidx((kk >> 14) & 0xFFu)], add);
            unsigned bal = __ballot_sync(FULLMASK, add != 0u);
            if (add) {
                unsigned pos = cnt + __popc(bal & ((1u << lane) - 1u));
                rowU[eBase + pos] = bb;      // pos < read frontier: in-warp safe
            }
            cnt += (unsigned)__popc(bal);
        }
    }
    chbar(bar);

    // L1 walks (q0 top / q1 bottom); bufA already clean
    if (q == 0) {
        int3 wt = walk(bufB, 0, lane, rT);
        rT = wt.y;
        if (lane == 0) spare[2] = ((unsigned)selT << 22) | ((unsigned)wt.x << 14);
    } else if (q == 1) {
        int3 wb = walk(bufB, 16, lane, rB);
        rB = wb.y;
        if (lane == 0) spare[3] = ((unsigned)selB << 22) | ((unsigned)wb.x << 14);
    }
    chbar(bar);
    unsigned pfxT = spare[2], pfxB = spare[3];
    const int citers = (int)((cnt + 31u) >> 5);

    // ---- L2 over compact list (bufA, bits 13..6) ---------------------------
#pragma unroll 1
    for (int i = 0; i < citers; i++) {
        unsigned idx = (unsigned)(i * 32 + lane);
        if (idx < cnt) {
            unsigned kk = mkey(rowU[eBase + idx]);
            unsigned hi18 = kk >> 14;
            unsigned add = ((hi18 == (pfxT >> 14)) ? 1u : 0u)
                         + ((hi18 == (pfxB >> 14)) ? 0x10000u : 0u);
            if (add) atomicAdd(&bufA[hidx((kk >> 6) & 0xFFu)], add);
        }
    }
    chbar(bar);

    // L2 walks; q2..q7 zero bufB for L3
    if (q == 0) {
        int3 wt = walk(bufA, 0, lane, rT);
        rT = wt.y;
        if (lane == 0) spare[2] = pfxT | ((unsigned)wt.x << 6);
    } else if (q == 1) {
        int3 wb = walk(bufA, 16, lane, rB);
        rB = wb.y;
        if (lane == 0) spare[3] = pfxB | ((unsigned)wb.x << 6);
    } else {
        for (int i = (q - 2) * 32 + lane; i < 384; i += 192) bufB[i] = 0;
    }
    chbar(bar);
    pfxT = spare[2]; pfxB = spare[3];

    // ---- L3 over compact list (bufB, bits 5..0 -> 64 bins) ------------------
#pragma unroll 1
    for (int i = 0; i < citers; i++) {
        unsigned idx = (unsigned)(i * 32 + lane);
        if (idx < cnt) {
            unsigned kk = mkey(rowU[eBase + idx]);
            unsigned hi26 = kk >> 6;
            unsigned add = ((hi26 == (pfxT >> 6)) ? 1u : 0u)
                         + ((hi26 == (pfxB >> 6)) ? 0x10000u : 0u);
            if (add) atomicAdd(&bufB[hidx(kk & 0x3Fu)], add);
        }
    }
    chbar(bar);

    if (q == 0) {
        int3 wt = walk(bufB, 0, lane, rT);   // bins 64..255 zero: harmless
        if (lane == 0) {
            spare[4] = __float_as_uint(key2f(pfxT | (unsigned)wt.x));
            spare[6] = (unsigned)wt.y;           // rT3
        }
    } else if (q == 1) {
        int3 wb = walk(bufB, 16, lane, rB);
        if (lane == 0) {
            spare[5] = __float_as_uint(key2f(pfxB | (unsigned)wb.x));
            spare[7] = (unsigned)(wb.y - wb.z);  // rB3 - eqB (signed)
        }
    }
    chbar(bar);
    const float vT = __uint_as_float(spare[4]);
    const float vB = __uint_as_float(spare[5]);

    // ---- stats tail over compact list (float compares) ---------------------
#pragma unroll 1
    for (int i = 0; i < citers; i++) {
        unsigned idx = (unsigned)(i * 32 + lane);
        if (idx < cnt) {
            float v = __uint_as_float(rowU[eBase + idx]);
            if (v > vT) sg += v;
            if (v < vB) sl += v;
        }
    }
    sg = wredf(sg);
    sl = wredf(sl);

    float* accF = reinterpret_cast<float*>(spare + 8);
    if (lane == 0) {
        atomicAdd(&accF[0], sg);
        atomicAdd(&accF[1], sl);
    }
    chbar(bar);

    if (q == 0 && lane == 0) {
        int rT3  = (int)spare[6];
        int rbme = (int)spare[7];            // rB3 - eqB (signed)
        int cg   = KSEL - rT3;               // strictly > vT
        int cl   = HWN - RBRANK + rbme;      // strictly < vB
        float Sg = accF[0], Sl = accF[1];
        float xmax = (Sg + (float)(KSEL - cg) * vT) * (1.0f / (float)KSEL);
        float xmin = (Sl + (float)(KSEL - cl) * vB) * (ALPHA / (float)KSEL);
        out[b * NCH + c0 + w] = 0.5f * (xmax + xmin);
    }
}

extern "C" void kernel_launch(void* const* d_in, const int* in_sizes, int n_in,
                              void* d_out, int out_size)
{
    const float* x = (const float*)d_in[0];
    float* out = (float*)d_out;
    cudaFuncSetAttribute(wildcat_kernel,
                         cudaFuncAttributeMaxDynamicSharedMemorySize,
                         SMEM_WORDS * (int)sizeof(unsigned));
    wildcat_kernel<<<NBATCH * (NCH / CPB), THREADS, SMEM_WORDS * sizeof(unsigned)>>>(x, out);
}

// round 16
// speedup vs baseline: 1.0346x; 1.0346x over previous
#include <cuda_runtime.h>
#include <cuda_bf16.h>
#include <stdint.h>

#define FULLMASK 0xFFFFFFFFu

constexpr int HWN     = 3136;   // 56*56
constexpr int NCH     = 512;
constexpr int NBATCH  = 32;
constexpr int CPB     = 4;      // channels per block (4 warps per channel)
constexpr int THREADS = 512;
constexpr int KSEL    = 627;    // round(0.2*3136)
constexpr int RBRANK  = HWN - KSEL + 1;  // bottom-end rank from largest
constexpr int STRIDE  = 3140;   // smem row stride (u32), 16B aligned
constexpr int NQ      = HWN / 4;        // 784 uint4 per row
constexpr int QQ      = NQ / 4;         // 196 uint4 per warp quarter
constexpr int QELEM   = QQ * 4;         // 784 elements per quarter
constexpr int H0SZ    = 1152;   // 1024 raw bins in 36-word groups
constexpr int HSTR    = H0SZ + 16;      // + spare; bufA/bufB overlay inside h0
constexpr int SMEM_WORDS = CPB * STRIDE + CPB * HSTR;
constexpr float ALPHA = 0.7f;

// monotone key <-> float
__device__ __forceinline__ float key2f(unsigned u) {
    return __uint_as_float((u & 0x80000000u) ? (u & 0x7FFFFFFFu) : ~u);
}
__device__ __forceinline__ unsigned mkey(unsigned b) {
    return b ^ ((unsigned)(((int)b) >> 31) | 0x80000000u);
}
// padded index: raw 1024-bin histo, 36 words per 32 bins
__device__ __forceinline__ int h0idx(unsigned bin) {
    return (int)(bin + ((bin >> 5) << 2));
}
// padded index: 256-bin histo, 12 words per 8 bins
__device__ __forceinline__ int hidx(unsigned bin) {
    return (int)(bin + ((bin >> 3) << 2));
}

__device__ __forceinline__ float wredf(float v) {
#pragma unroll
    for (int d = 16; d; d >>= 1) v += __shfl_xor_sync(FULLMASK, v, d);
    return v;
}

// per-channel barrier: 4 warps (128 threads), barrier id = channel+1
__device__ __forceinline__ void chbar(int id) {
    asm volatile("bar.sync %0, %1;" :: "r"(id), "r"(128) : "memory");
}

// ---- 1024-bin walk over RAW-bin padded layout, traversed in DESCENDING value
// order. Desc order: raw 511..0 (positives), then raw 512..1023 (negatives).
// rank r is 1-based from the largest value. Returns (sortedBin, rankInBin, binCount)
// where sortedBin = mkey-style bin (1023 = largest).
__device__ __forceinline__ int3 walk1024d(const unsigned* h, int lane, int r)
{
    // stage 1: lane covers desc positions [lane*32, lane*32+32)
    int pg = (lane < 16) ? (15 - lane) : lane;           // physical raw group
    const uint4* hv = reinterpret_cast<const uint4*>(h) + pg * 9; // 36 words/group
    int s = 0;
#pragma unroll
    for (int j = 0; j < 8; j++) { uint4 u = hv[j]; s += (int)(u.x + u.y + u.z + u.w); }
    // exclusive prefix over lanes < lane (lane 0 = largest values)
    int excl = s;
#pragma unroll
    for (int d = 1; d < 32; d <<= 1) {
        int v = __shfl_up_sync(FULLMASK, excl, d);
        if (lane >= d) excl += v;
    }
    excl -= s;
    bool sel = (excl < r) && (r <= excl + s);
    unsigned bal = __ballot_sync(FULLMASK, sel);
    int L = __ffs((int)bal) - 1;
    int rloc = __shfl_sync(FULLMASK, r - excl, L);
    // stage 2: desc position L*32+lane -> raw physical index
    int idx = (L < 16) ? ((15 - L) * 36 + (31 - lane)) : (L * 36 + lane);
    int c2 = (int)h[idx];
    int excl2 = c2;
#pragma unroll
    for (int d = 1; d < 32; d <<= 1) {
        int v = __shfl_up_sync(FULLMASK, excl2, d);
        if (lane >= d) excl2 += v;
    }
    excl2 -= c2;
    bool sel2 = (excl2 < rloc) && (rloc <= excl2 + c2);
    unsigned bal2 = __ballot_sync(FULLMASK, sel2);
    int L2 = __ffs((int)bal2) - 1;
    int p  = L * 32 + L2;                    // desc position
    int rr = __shfl_sync(FULLMASK, rloc - excl2, L2);
    int cc = __shfl_sync(FULLMASK, c2, L2);
    return make_int3(1023 - p, rr, cc);      // sorted (key-order) bin
}

// ---- 256-bin packed walk over 12-word-padded layout (low16/high16 by shift).
// Ascending key layout; rank from largest. Returns (bin, rankInBin, countOfBin).
__device__ __forceinline__ int3 walk(const unsigned* hist, int shift, int lane, int r)
{
    const uint4* hv = reinterpret_cast<const uint4*>(hist) + lane * 3; // 12 words
    uint4 a = hv[0], bq = hv[1];
    unsigned c[8] = { (a.x  >> shift) & 0xFFFFu, (a.y  >> shift) & 0xFFFFu,
                      (a.z  >> shift) & 0xFFFFu, (a.w  >> shift) & 0xFFFFu,
                      (bq.x >> shift) & 0xFFFFu, (bq.y >> shift) & 0xFFFFu,
                      (bq.z >> shift) & 0xFFFFu, (bq.w >> shift) & 0xFFFFu };
    int s = 0;
#pragma unroll
    for (int j = 0; j < 8; j++) s += (int)c[j];
    int incl = s;                            // suffix sum: lanes >= lane
#pragma unroll
    for (int d = 1; d < 32; d <<= 1) {
        int v = __shfl_down_sync(FULLMASK, incl, d);
        if (lane + d < 32) incl += v;
    }
    int hi = incl - s;
    bool sel = (hi < r) && (r <= hi + s);
    unsigned bal = __ballot_sync(FULLMASK, sel);
    int L = __ffs((int)bal) - 1;
    int bin = -1, rr = 0, cc = 0;
    if (lane == L) {
        int rloc = r - hi, cum = 0;
#pragma unroll
        for (int j = 7; j >= 0; j--) {
            if (bin < 0 && rloc <= cum + (int)c[j]) { bin = j; rr = rloc - cum; cc = (int)c[j]; }
            cum += (int)c[j];
        }
        bin += lane * 8;
    }
    bin = __shfl_sync(FULLMASK, bin, L);
    rr  = __shfl_sync(FULLMASK, rr,  L);
    cc  = __shfl_sync(FULLMASK, cc,  L);
    return make_int3(bin, rr, cc);
}

extern __shared__ unsigned smem[];

__global__ void __launch_bounds__(THREADS, 3)
wildcat_kernel(const float* __restrict__ x, float* __restrict__ out)
{
    unsigned* vals = smem;                   // CPB * STRIDE (raw float bits)
    unsigned* hist = smem + CPB * STRIDE;    // CPB * HSTR

    const int t    = threadIdx.x;
    const int lane = t & 31;
    const int warp = t >> 5;                 // 0..15
    const int w    = warp >> 2;              // channel 0..3
    const int q    = warp & 3;               // quarter of the spatial row
    const int bar  = w + 1;
    const int b    = blockIdx.x >> 7;        // batch
    const int c0   = (blockIdx.x & 127) * CPB;

    for (int i = t; i < CPB * HSTR; i += THREADS) hist[i] = 0;
    __syncthreads();

    // ---- load + transpose + FUSED raw-bin L0 histogram (b>>22, 1 op) -------
    {
        const float4* src = reinterpret_cast<const float4*>(
            x + (size_t)b * HWN * NCH + c0);
#pragma unroll 2
        for (int i = 0; i < 6; i++) {        // 6 full, unconditional iterations
            int hw = t + i * 512;
            float4 v = src[(size_t)hw * (NCH / 4)];
            unsigned k0 = __float_as_uint(v.x), k1 = __float_as_uint(v.y);
            unsigned k2 = __float_as_uint(v.z), k3 = __float_as_uint(v.w);
            vals[0 * STRIDE + hw] = k0;
            vals[1 * STRIDE + hw] = k1;
            vals[2 * STRIDE + hw] = k2;
            vals[3 * STRIDE + hw] = k3;
            atomicAdd(&hist[0 * HSTR + h0idx(k0 >> 22)], 1u);
            atomicAdd(&hist[1 * HSTR + h0idx(k1 >> 22)], 1u);
            atomicAdd(&hist[2 * HSTR + h0idx(k2 >> 22)], 1u);
            atomicAdd(&hist[3 * HSTR + h0idx(k3 >> 22)], 1u);
        }
        if (t < 64) {                        // tail: hw in [3072, 3136)
            int hw = t + 3072;
            float4 v = src[(size_t)hw * (NCH / 4)];
            unsigned k0 = __float_as_uint(v.x), k1 = __float_as_uint(v.y);
            unsigned k2 = __float_as_uint(v.z), k3 = __float_as_uint(v.w);
            vals[0 * STRIDE + hw] = k0;
            vals[1 * STRIDE + hw] = k1;
            vals[2 * STRIDE + hw] = k2;
            vals[3 * STRIDE + hw] = k3;
            atomicAdd(&hist[0 * HSTR + h0idx(k0 >> 22)], 1u);
            atomicAdd(&hist[1 * HSTR + h0idx(k1 >> 22)], 1u);
            atomicAdd(&hist[2 * HSTR + h0idx(k2 >> 22)], 1u);
            atomicAdd(&hist[3 * HSTR + h0idx(k3 >> 22)], 1u);
        }
    }
    __syncthreads();                         // last block-wide barrier

    // ---- per-channel selection ---------------------------------------------
    unsigned* rowU  = vals + w * STRIDE;
    const uint4* row4 = reinterpret_cast<const uint4*>(rowU);
    unsigned* h0    = hist + w * HSTR;       // raw 1024-bin L0 (padded)
    unsigned* bufA  = h0;                    // overlay after L0 walk (384 words)
    unsigned* bufB  = h0 + 384;              // overlay (384 words)
    unsigned* spare = h0 + H0SZ;             // 16 words, outside overlay
    const int qBase = q * QQ;
    const int eBase = q * QELEM;
    const int cid   = (q << 5) | lane;       // 0..127 within channel

    int rT = 0;                              // live in q0
    int rB = 0;                              // live in q1

    // L0 walks: top on q0, bottom on q1. Publish sorted bin + float boundaries.
    // NOTE: boundary keys assume selected bins are finite-float bins (gaussian
    // data: |x| < ~6, far from inf/NaN bins), so key2f boundaries are finite.
    if (q == 0) {
        int3 st = walk1024d(h0, lane, KSEL);
        rT = st.y;
        if (lane == 0) {
            unsigned s = (unsigned)st.x;
            spare[0] = s;                                        // sortedT
            spare[2] = __float_as_uint(key2f(s << 22));          // fLoT
            spare[3] = __float_as_uint(key2f((s << 22) + 0x3FFFFFu)); // fHiT
        }
    } else if (q == 1) {
        int3 sb = walk1024d(h0, lane, RBRANK);
        rB = sb.y;
        if (lane == 0) {
            unsigned s = (unsigned)sb.x;
            spare[1] = s;                                        // sortedB
            spare[4] = __float_as_uint(key2f(s << 22));          // fLoB
            spare[5] = __float_as_uint(key2f((s << 22) + 0x3FFFFFu)); // fHiB
        }
    }
    chbar(bar);
    const unsigned sortedT = spare[0], sortedB = spare[1];
    const float fLoT = __uint_as_float(spare[2]);
    const float fHiT = __uint_as_float(spare[3]);
    const float fLoB = __uint_as_float(spare[4]);
    const float fHiB = __uint_as_float(spare[5]);

    // zero bufB (L0 hist is dead now); bufA zeroed later, overlapped
    for (int i = cid; i < 384; i += 128) bufB[i] = 0;
    chbar(bar);

    // ---- L1: full scan with FLOAT classification; compact kk of candidates -
    float sg = 0.f, sl = 0.f;
    unsigned cnt = 0;                        // compacted count (warp-uniform)
#pragma unroll 1
    for (int i = 0; i < 7; i++) {
        const bool valid = (i < 6) || (lane < (QQ - 192));
        uint4 kv = valid ? row4[qBase + i * 32 + lane] : make_uint4(0u, 0u, 0u, 0u);
        unsigned ks[4] = {kv.x, kv.y, kv.z, kv.w};
#pragma unroll
        for (int e = 0; e < 4; e++) {
            float v = __uint_as_float(ks[e]);
            bool sureT = valid && (v > fHiT);
            bool candT = valid && (v >= fLoT) && (v <= fHiT);
            bool sureB = valid && (v < fLoB);
            bool candB = valid && (v >= fLoB) && (v <= fHiB);
            if (sureT) sg += v;
            if (sureB) sl += v;
            bool cand = candT || candB;
            unsigned kk = 0;
            if (cand) {
                kk = mkey(ks[e]);
                unsigned add = (candT ? 1u : 0u) + (candB ? 0x10000u : 0u);
                atomicAdd(&bufB[hidx((kk >> 14) & 0xFFu)], add);
            }
            unsigned bal = __ballot_sync(FULLMASK, cand);
            if (cand) {
                unsigned pos = cnt + __popc(bal & ((1u << lane) - 1u));
                rowU[eBase + pos] = kk;      // store KEY; pos < read frontier
            }
            cnt += (unsigned)__popc(bal);
        }
    }
    chbar(bar);

    // L1 walks (q0 top / q1 bottom) overlapped with zeroing bufA (q2/q3)
    if (q == 0) {
        int3 wt = walk(bufB, 0, lane, rT);
        rT = wt.y;
        if (lane == 0) spare[6] = (sortedT << 22) | ((unsigned)wt.x << 14);
    } else if (q == 1) {
        int3 wb = walk(bufB, 16, lane, rB);
        rB = wb.y;
        if (lane == 0) spare[7] = (sortedB << 22) | ((unsigned)wb.x << 14);
    } else {
        for (int i = (q - 2) * 32 + lane; i < 384; i += 64) bufA[i] = 0;
    }
    chbar(bar);
    unsigned pfxT = spare[6], pfxB = spare[7];
    const int citers = (int)((cnt + 31u) >> 5);

    // ---- L2 over compact key list (bufA, bits 13..6) ------------------------
#pragma unroll 1
    for (int i = 0; i < citers; i++) {
        unsigned idx = (unsigned)(i * 32 + lane);
        if (idx < cnt) {
            unsigned kk = rowU[eBase + idx];
            unsigned hi18 = kk >> 14;
            unsigned add = ((hi18 == (pfxT >> 14)) ? 1u : 0u)
                         + ((hi18 == (pfxB >> 14)) ? 0x10000u : 0u);
            if (add) atomicAdd(&bufA[hidx((kk >> 6) & 0xFFu)], add);
        }
    }
    chbar(bar);

    // L2 walks; q2/q3 zero bufB for L3
    if (q == 0) {
        int3 wt = walk(bufA, 0, lane, rT);
        rT = wt.y;
        if (lane == 0) spare[6] = pfxT | ((unsigned)wt.x << 6);
    } else if (q == 1) {
        int3 wb = walk(bufA, 16, lane, rB);
        rB = wb.y;
        if (lane == 0) spare[7] = pfxB | ((unsigned)wb.x << 6);
    } else {
        for (int i = (q - 2) * 32 + lane; i < 384; i += 64) bufB[i] = 0;
    }
    chbar(bar);
    pfxT = spare[6]; pfxB = spare[7];

    // ---- L3 over compact key list (bufB, bits 5..0 -> 64 bins) --------------
#pragma unroll 1
    for (int i = 0; i < citers; i++) {
        unsigned idx = (unsigned)(i * 32 + lane);
        if (idx < cnt) {
            unsigned kk = rowU[eBase + idx];
            unsigned hi26 = kk >> 6;
            unsigned add = ((hi26 == (pfxT >> 6)) ? 1u : 0u)
                         + ((hi26 == (pfxB >> 6)) ? 0x10000u : 0u);
            if (add) atomicAdd(&bufB[hidx(kk & 0x3Fu)], add);
        }
    }
    chbar(bar);

    if (q == 0) {
        int3 wt = walk(bufB, 0, lane, rT);   // bins 64..255 zero: harmless
        if (lane == 0) {
            spare[8]  = pfxT | (unsigned)wt.x;   // exact key of k-th largest
            spare[10] = (unsigned)wt.y;          // rT3
        }
    } else if (q == 1) {
        int3 wb = walk(bufB, 16, lane, rB);
        if (lane == 0) {
            spare[9]  = pfxB | (unsigned)wb.x;   // exact key of k-th smallest
            spare[11] = (unsigned)(wb.y - wb.z); // rB3 - eqB (signed)
        }
    }
    chbar(bar);
    const unsigned kT = spare[8];
    const unsigned kB = spare[9];

    // ---- stats tail over compact key list (unsigned compares) --------------
#pragma unroll 1
    for (int i = 0; i < citers; i++) {
        unsigned idx = (unsigned)(i * 32 + lane);
        if (idx < cnt) {
            unsigned kk = rowU[eBase + idx];
            float v = key2f(kk);
            if (kk > kT) sg += v;
            if (kk < kB) sl += v;
        }
    }
    sg = wredf(sg);
    sl = wredf(sl);

    float* accF = reinterpret_cast<float*>(spare + 12);   // zeroed at init
    if (lane == 0) {
        atomicAdd(&accF[0], sg);
        atomicAdd(&accF[1], sl);
    }
    chbar(bar);

    if (q == 0 && lane == 0) {
        int rT3  = (int)spare[10];
        int rbme = (int)spare[11];           // rB3 - eqB (signed)
        int cg   = KSEL - rT3;               // strictly > vT
        int cl   = HWN - RBRANK + rbme;      // strictly < vB
        float vT = key2f(kT), vB = key2f(kB);
        float Sg = accF[0], Sl = accF[1];
        float xmax = (Sg + (float)(KSEL - cg) * vT) * (1.0f / (float)KSEL);
        float xmin = (Sl + (float)(KSEL - cl) * vB) * (ALPHA / (float)KSEL);
        out[b * NCH + c0 + w] = 0.5f * (xmax + xmin);
    }
}

extern "C" void kernel_launch(void* const* d_in, const int* in_sizes, int n_in,
                              void* d_out, int out_size)
{
    const float* x = (const float*)d_in[0];
    float* out = (float*)d_out;
    cudaFuncSetAttribute(wildcat_kernel,
                         cudaFuncAttributeMaxDynamicSharedMemorySize,
                         SMEM_WORDS * (int)sizeof(unsigned));
    wildcat_kernel<<<NBATCH * (NCH / CPB), THREADS, SMEM_WORDS * sizeof(unsigned)>>>(x, out);
}

// round 17
// speedup vs baseline: 1.1218x; 1.0843x over previous
#include <cuda_runtime.h>
#include <cuda_bf16.h>
#include <stdint.h>

#define FULLMASK 0xFFFFFFFFu

constexpr int HWN     = 3136;   // 56*56
constexpr int NCH     = 512;
constexpr int NBATCH  = 32;
constexpr int CPB     = 4;      // channels per block (4 warps per channel)
constexpr int THREADS = 512;
constexpr int KSEL    = 627;    // round(0.2*3136)
constexpr int STRIDE  = 3140;   // smem row stride (u32), 16B aligned
constexpr int NQ      = HWN / 4;        // 784 uint4 per row
constexpr int QQ      = NQ / 4;         // 196 uint4 per warp quarter
constexpr int QELEM   = QQ * 4;         // 784 elements per quarter
constexpr int HSTR    = 800;    // 384 (bufA) + 384 (bufB) + 32 spare
constexpr int SMEM_WORDS = CPB * STRIDE + CPB * HSTR;
constexpr float ALPHA = 0.7f;

// fixed probe keys (monotone key space)
constexpr unsigned KT_HI  = 0xBF800000u;  // key(+1.0f)
constexpr unsigned KT_LO  = 0xBF333333u;  // key(+0.7f)
constexpr unsigned KB_LOK = 0x407FFFFFu;  // key(-1.0f)
constexpr unsigned KB_HIK = 0x40CCCCCCu;  // key(-0.7f)

__device__ __forceinline__ float key2f(unsigned u) {
    return __uint_as_float((u & 0x80000000u) ? (u & 0x7FFFFFFFu) : ~u);
}
__device__ __forceinline__ unsigned mkey(unsigned b) {
    return b ^ ((unsigned)(((int)b) >> 31) | 0x80000000u);
}
// padded index: 256-bin histo, 12 words per 8 bins (conflict-free walk)
__device__ __forceinline__ int hidx(unsigned bin) {
    return (int)(bin + ((bin >> 3) << 2));
}

__device__ __forceinline__ int wredi(int v) {
#pragma unroll
    for (int d = 16; d; d >>= 1) v += __shfl_xor_sync(FULLMASK, v, d);
    return v;
}
__device__ __forceinline__ float wredf(float v) {
#pragma unroll
    for (int d = 16; d; d >>= 1) v += __shfl_xor_sync(FULLMASK, v, d);
    return v;
}

// per-channel barrier: 4 warps (128 threads), barrier id = channel+1
__device__ __forceinline__ void chbar(int id) {
    asm volatile("bar.sync %0, %1;" :: "r"(id), "r"(128) : "memory");
}

// ---- 256-bin packed walk over 12-word-padded layout (low16/high16 by shift).
// Ascending-bin layout; rank r 1-based FROM LARGEST. Returns (bin, rankInBin, cnt).
__device__ __forceinline__ int3 walk(const unsigned* hist, int shift, int lane, int r)
{
    const uint4* hv = reinterpret_cast<const uint4*>(hist) + lane * 3; // 12 words
    uint4 a = hv[0], bq = hv[1];
    unsigned c[8] = { (a.x  >> shift) & 0xFFFFu, (a.y  >> shift) & 0xFFFFu,
                      (a.z  >> shift) & 0xFFFFu, (a.w  >> shift) & 0xFFFFu,
                      (bq.x >> shift) & 0xFFFFu, (bq.y >> shift) & 0xFFFFu,
                      (bq.z >> shift) & 0xFFFFu, (bq.w >> shift) & 0xFFFFu };
    int s = 0;
#pragma unroll
    for (int j = 0; j < 8; j++) s += (int)c[j];
    int incl = s;                            // suffix sum: lanes >= lane
#pragma unroll
    for (int d = 1; d < 32; d <<= 1) {
        int v = __shfl_down_sync(FULLMASK, incl, d);
        if (lane + d < 32) incl += v;
    }
    int hi = incl - s;
    bool sel = (hi < r) && (r <= hi + s);
    unsigned bal = __ballot_sync(FULLMASK, sel);
    int L = __ffs((int)bal) - 1;
    int bin = -1, rr = 0, cc = 0;
    if (lane == L) {
        int rloc = r - hi, cum = 0;
#pragma unroll
        for (int j = 7; j >= 0; j--) {
            if (bin < 0 && rloc <= cum + (int)c[j]) { bin = j; rr = rloc - cum; cc = (int)c[j]; }
            cum += (int)c[j];
        }
        bin += lane * 8;
    }
    bin = __shfl_sync(FULLMASK, bin, L);
    rr  = __shfl_sync(FULLMASK, rr,  L);
    cc  = __shfl_sync(FULLMASK, cc,  L);
    return make_int3(bin, rr, cc);
}

extern __shared__ unsigned smem[];

__global__ void __launch_bounds__(THREADS, 3)
wildcat_kernel(const float* __restrict__ x, float* __restrict__ out)
{
    unsigned* vals = smem;                   // CPB * STRIDE (raw float bits)
    unsigned* hist = smem + CPB * STRIDE;    // CPB * HSTR

    const int t    = threadIdx.x;
    const int lane = t & 31;
    const int warp = t >> 5;                 // 0..15
    const int w    = warp >> 2;              // channel 0..3
    const int q    = warp & 3;               // quarter of the spatial row
    const int bar  = w + 1;
    const int b    = blockIdx.x >> 7;        // batch
    const int c0   = (blockIdx.x & 127) * CPB;

    for (int i = t; i < CPB * HSTR; i += THREADS) hist[i] = 0;
    __syncthreads();

    // ---- load + transpose + FUSED 4-threshold counters (NO atomics) --------
    // Per slot e (= channel), byte-packed counts: b0:v>1, b8:v>0.7, b16:v<-1, b24:v<-0.7
    unsigned pc0 = 0, pc1 = 0, pc2 = 0, pc3 = 0;
    {
        const float4* src = reinterpret_cast<const float4*>(
            x + (size_t)b * HWN * NCH + c0);
#pragma unroll 2
        for (int i = 0; i < 6; i++) {
            int hw = t + i * 512;
            float4 v = src[(size_t)hw * (NCH / 4)];
            vals[0 * STRIDE + hw] = __float_as_uint(v.x);
            vals[1 * STRIDE + hw] = __float_as_uint(v.y);
            vals[2 * STRIDE + hw] = __float_as_uint(v.z);
            vals[3 * STRIDE + hw] = __float_as_uint(v.w);
            if (v.x >  1.0f) pc0 += 1u;        if (v.x >  0.7f) pc0 += 1u << 8;
            if (v.x < -1.0f) pc0 += 1u << 16;  if (v.x < -0.7f) pc0 += 1u << 24;
            if (v.y >  1.0f) pc1 += 1u;        if (v.y >  0.7f) pc1 += 1u << 8;
            if (v.y < -1.0f) pc1 += 1u << 16;  if (v.y < -0.7f) pc1 += 1u << 24;
            if (v.z >  1.0f) pc2 += 1u;        if (v.z >  0.7f) pc2 += 1u << 8;
            if (v.z < -1.0f) pc2 += 1u << 16;  if (v.z < -0.7f) pc2 += 1u << 24;
            if (v.w >  1.0f) pc3 += 1u;        if (v.w >  0.7f) pc3 += 1u << 8;
            if (v.w < -1.0f) pc3 += 1u << 16;  if (v.w < -0.7f) pc3 += 1u << 24;
        }
        if (t < 64) {                        // tail: hw in [3072, 3136)
            int hw = t + 3072;
            float4 v = src[(size_t)hw * (NCH / 4)];
            vals[0 * STRIDE + hw] = __float_as_uint(v.x);
            vals[1 * STRIDE + hw] = __float_as_uint(v.y);
            vals[2 * STRIDE + hw] = __float_as_uint(v.z);
            vals[3 * STRIDE + hw] = __float_as_uint(v.w);
            if (v.x >  1.0f) pc0 += 1u;        if (v.x >  0.7f) pc0 += 1u << 8;
            if (v.x < -1.0f) pc0 += 1u << 16;  if (v.x < -0.7f) pc0 += 1u << 24;
            if (v.y >  1.0f) pc1 += 1u;        if (v.y >  0.7f) pc1 += 1u << 8;
            if (v.y < -1.0f) pc1 += 1u << 16;  if (v.y < -0.7f) pc1 += 1u << 24;
            if (v.z >  1.0f) pc2 += 1u;        if (v.z >  0.7f) pc2 += 1u << 8;
            if (v.z < -1.0f) pc2 += 1u << 16;  if (v.z < -0.7f) pc2 += 1u << 24;
            if (v.w >  1.0f) pc3 += 1u;        if (v.w >  0.7f) pc3 += 1u << 8;
            if (v.w < -1.0f) pc3 += 1u << 16;  if (v.w < -0.7f) pc3 += 1u << 24;
        }
    }
    // warp-reduce packed counts (byte sums <= 224, no carry), 2 atomics per slot
    pc0 = (unsigned)wredi((int)pc0);
    pc1 = (unsigned)wredi((int)pc1);
    pc2 = (unsigned)wredi((int)pc2);
    pc3 = (unsigned)wredi((int)pc3);
    if (lane == 0) {
        unsigned pcs[4] = {pc0, pc1, pc2, pc3};
#pragma unroll
        for (int e = 0; e < 4; e++) {
            unsigned r = pcs[e];
            atomicAdd(&hist[e * HSTR + 768 + 17], ((r & 0xFFu) << 16) | ((r >> 8) & 0xFFu));
            atomicAdd(&hist[e * HSTR + 768 + 18], (((r >> 16) & 0xFFu) << 16) | ((r >> 24) & 0xFFu));
        }
    }
    __syncthreads();                         // last block-wide barrier

    // ---- per-channel pointers ----------------------------------------------
    unsigned* rowU  = vals + w * STRIDE;
    const uint4* row4 = reinterpret_cast<const uint4*>(rowU);
    unsigned* bufA  = hist + w * HSTR;       // 384 words (padded 256-bin)
    unsigned* bufB  = bufA + 384;            // 384 words
    unsigned* spare = bufA + 768;            // 32 words
    const int qBase = q * QQ;
    const int eBase = q * QELEM;

    // ---- bracket resolution (q0 lane0): exact for ANY data -----------------
    if (q == 0 && lane == 0) {
        unsigned ct = spare[17], cb = spare[18];
        int cH = (int)(ct >> 16), c07 = (int)(ct & 0xFFFFu);
        unsigned lo1, hi; int r;
        if (cH >= KSEL)       { lo1 = KT_HI + 1; hi = 0xFFFFFFFFu; r = KSEL; }
        else if (c07 >= KSEL) { lo1 = KT_LO + 1; hi = KT_HI;       r = KSEL - cH; }
        else                  { lo1 = 0u;        hi = KT_LO;       r = KSEL - c07; }
        unsigned W = hi - lo1;
        int nb = W ? (32 - __clz((int)W)) : 0;
        int LT = nb ? ((nb + 7) >> 3) : 1;
        spare[0] = lo1; spare[1] = hi;
        spare[4] = __float_as_uint(key2f(lo1));
        spare[5] = __float_as_uint(key2f(hi));
        spare[8] = (unsigned)LT;
        spare[11] = (unsigned)r;
        int cLb = (int)(cb >> 16), c07b = (int)(cb & 0xFFFFu);
        unsigned lo1b, hib; int ra, bc;
        if (cLb >= KSEL)       { lo1b = 0u;      hib = KB_LOK - 1;  ra = KSEL;        bc = cLb; }
        else if (c07b >= KSEL) { lo1b = KB_LOK;  hib = KB_HIK - 1;  ra = KSEL - cLb;  bc = c07b - cLb; }
        else                   { lo1b = KB_HIK;  hib = 0xFFFFFFFFu; ra = KSEL - c07b; bc = HWN - c07b; }
        unsigned Wb = hib - lo1b;
        int nbB = Wb ? (32 - __clz((int)Wb)) : 0;
        int LB = nbB ? ((nbB + 7) >> 3) : 1;
        spare[2] = lo1b; spare[3] = hib;
        spare[6] = __float_as_uint(key2f(lo1b));
        spare[7] = __float_as_uint(key2f(hib));
        spare[9] = (unsigned)LB;
        spare[10] = (unsigned)(LT > LB ? LT : LB);
        spare[12] = (unsigned)(bc - ra + 1);     // rank within bracket, descending
    }
    chbar(bar);
    unsigned lo1T = spare[0], hiT = spare[1], lo1B = spare[2], hiB = spare[3];
    const float fLo1T = __uint_as_float(spare[4]);
    const float fHiT  = __uint_as_float(spare[5]);
    const float fLo1B = __uint_as_float(spare[6]);
    const float fHiB  = __uint_as_float(spare[7]);
    const int LT = (int)spare[8], LB = (int)spare[9], maxL = (int)spare[10];
    int rT  = (int)spare[11];                // used by q0 walks
    int rBd = (int)spare[12];                // used by q1 walks
    const int sT0 = 8 * (LT - 1);
    const int sB0 = 8 * (LB - 1);

    // ---- scan: sure-sums + candidate compaction + level-0 hist (bufB) ------
    float sg = 0.f, sl = 0.f;
    unsigned cnt = 0;
#pragma unroll 1
    for (int i = 0; i < 7; i++) {
        const bool valid = (i < 6) || (lane < (QQ - 192));
        uint4 kv = valid ? row4[qBase + i * 32 + lane] : make_uint4(0u, 0u, 0u, 0u);
        unsigned ks[4] = {kv.x, kv.y, kv.z, kv.w};
#pragma unroll
        for (int e = 0; e < 4; e++) {
            unsigned bb = ks[e];
            float v = __uint_as_float(bb);
            bool gtHi = v > fHiT;            // sure-top (false when fHiT is NaN sentinel)
            bool ltLo = v < fLo1B;           // sure-bottom
            if (valid && gtHi) sg += v;
            if (valid && ltLo) sl += v;
            bool candT = valid && !(v < fLo1T) && !gtHi;
            bool candB = valid && !(v > fHiB) && !ltLo;
            bool cand = candT || candB;
            unsigned kk = 0;
            if (cand) {
                kk = mkey(bb);
                if (candT) atomicAdd(&bufB[hidx(((kk - lo1T) >> sT0) & 0xFFu)], 1u);
                if (candB) atomicAdd(&bufB[hidx(((kk - lo1B) >> sB0) & 0xFFu)], 0x10000u);
            }
            unsigned bal = __ballot_sync(FULLMASK, cand);
            if (cand) {
                unsigned pos = cnt + __popc(bal & ((1u << lane) - 1u));
                rowU[eBase + pos] = kk;      // pos < read frontier: in-warp safe
            }
            cnt += (unsigned)__popc(bal);
        }
    }
    chbar(bar);
    const int citers = (int)((cnt + 31u) >> 5);

    // ---- refinement levels: walk (q0 top / q1 bottom / q2+ zero) + hist ----
#pragma unroll 1
    for (int lvl = 0; lvl < maxL; lvl++) {
        unsigned* hb = (lvl & 1) ? bufA : bufB;
        unsigned* ho = (lvl & 1) ? bufB : bufA;
        if (q == 0) {
            if (lvl < LT) {
                int s = 8 * (LT - 1 - lvl);
                int3 wt = walk(hb, 0, lane, rT);
                rT = wt.y;
                if (lane == 0) {
                    unsigned nlo = lo1T + ((unsigned)wt.x << s);
                    spare[0] = nlo;
                    spare[1] = s ? (nlo + (1u << s) - 1u) : nlo;
                    if (s == 0) spare[13] = (unsigned)wt.y;       // rT3
                }
            }
        } else if (q == 1) {
            if (lvl < LB) {
                int s = 8 * (LB - 1 - lvl);
                int3 wb = walk(hb, 16, lane, rBd);
                rBd = wb.y;
                if (lane == 0) {
                    unsigned nlo = lo1B + ((unsigned)wb.x << s);
                    spare[2] = nlo;
                    spare[3] = s ? (nlo + (1u << s) - 1u) : nlo;
                    if (s == 0) spare[14] = (unsigned)(wb.y - wb.z);  // rB3 - eq
                }
            }
        } else {
            for (int i = (q - 2) * 32 + lane; i < 384; i += 64) ho[i] = 0;
        }
        chbar(bar);
        lo1T = spare[0]; hiT = spare[1]; lo1B = spare[2]; hiB = spare[3];
        if (lvl + 1 < maxL) {
            int sTn = (lvl + 1 < LT) ? 8 * (LT - 2 - lvl) : -1;
            int sBn = (lvl + 1 < LB) ? 8 * (LB - 2 - lvl) : -1;
#pragma unroll 1
            for (int i = 0; i < citers; i++) {
                unsigned idx = (unsigned)(i * 32 + lane);
                if (idx < cnt) {
                    unsigned kk = rowU[eBase + idx];
                    if (sTn >= 0 && kk >= lo1T && kk <= hiT)
                        atomicAdd(&ho[hidx(((kk - lo1T) >> sTn) & 0xFFu)], 1u);
                    if (sBn >= 0 && kk >= lo1B && kk <= hiB)
                        atomicAdd(&ho[hidx(((kk - lo1B) >> sBn) & 0xFFu)], 0x10000u);
                }
            }
            chbar(bar);
        }
    }
    const unsigned kTex = lo1T;              // exact key of k-th largest
    const unsigned kBex = lo1B;              // exact key of k-th smallest

    // ---- stats tail over compact key list ----------------------------------
#pragma unroll 1
    for (int i = 0; i < citers; i++) {
        unsigned idx = (unsigned)(i * 32 + lane);
        if (idx < cnt) {
            unsigned kk = rowU[eBase + idx];
            float v = key2f(kk);
            if (kk > kTex) sg += v;
            if (kk < kBex) sl += v;
        }
    }
    sg = wredf(sg);
    sl = wredf(sl);

    float* accF = reinterpret_cast<float*>(spare + 15);   // zeroed at init
    if (lane == 0) {
        atomicAdd(&accF[0], sg);
        atomicAdd(&accF[1], sl);
    }
    chbar(bar);

    if (q == 0 && lane == 0) {
        int rT3  = (int)spare[13];
        int rbme = (int)spare[14];           // rB3 - eq (signed)
        float vT = key2f(kTex), vB = key2f(kBex);
        float Sg = accF[0], Sl = accF[1];
        // cg = KSEL - rT3 -> (KSEL - cg) = rT3 ; cl = KSEL-1+rbme -> (KSEL - cl) = 1 - rbme
        float xmax = (Sg + (float)rT3 * vT) * (1.0f / (float)KSEL);
        float xmin = (Sl + (float)(1 - rbme) * vB) * (ALPHA / (float)KSEL);
        out[b * NCH + c0 + w] = 0.5f * (xmax + xmin);
    }
}

extern "C" void kernel_launch(void* const* d_in, const int* in_sizes, int n_in,
                              void* d_out, int out_size)
{
    const float* x = (const float*)d_in[0];
    float* out = (float*)d_out;
    cudaFuncSetAttribute(wildcat_kernel,
                         cudaFuncAttributeMaxDynamicSharedMemorySize,
                         SMEM_WORDS * (int)sizeof(unsigned));
    wildcat_kernel<<<NBATCH * (NCH / CPB), THREADS, SMEM_WORDS * sizeof(unsigned)>>>(x, out);
}